// round 16
// baseline (speedup 1.0000x reference)
#include <cuda_runtime.h>
#include <cuda_fp16.h>
#include <math.h>

#define BB 4096
#define SS 200
#define DD 64
#define VV 100000
#define ROWH 32      // halfs per g_proj row (64B stride): g[5], q[18], pad
#define MSTRIDE 12   // floats per staged main row (48B) -> perfect bank tiling

#define PTILE   64   // vocab rows per proj tile
#define PGRID   740  // 5 blocks/SM exactly
#define PSTRIDE 68   // floats per staged proj row: 68 mod 32 = 4 -> conflict-free frags
#define NTILES  ((VV + PTILE - 1) / PTILE)   // 1563

// Static device scratch (allocation-free per harness rules)
__device__ __align__(128) __half g_proj[(size_t)VV * ROWH];
__device__ float g_loss[BB];

__device__ __forceinline__ float fast_tanh(float x) {
    float ax = fabsf(x);
    float t  = __expf(-2.0f * ax);
    float r  = __fdividef(1.0f - t, 1.0f + t);
    return copysignf(r, x);
}

__device__ __forceinline__ unsigned tf32_rna(float x) {
    unsigned r;
    asm("cvt.rna.tf32.f32 %0, %1;" : "=r"(r) : "f"(x));
    return r;
}

__device__ __forceinline__ void mma_tf32(float* c, const unsigned* a, const unsigned* b) {
    asm volatile(
        "mma.sync.aligned.m16n8k8.row.col.f32.tf32.tf32.f32 "
        "{%0,%1,%2,%3}, {%4,%5,%6,%7}, {%8,%9}, {%0,%1,%2,%3};\n"
        : "+f"(c[0]), "+f"(c[1]), "+f"(c[2]), "+f"(c[3])
        : "r"(a[0]), "r"(a[1]), "r"(a[2]), "r"(a[3]), "r"(b[0]), "r"(b[1]));
}

// ---------------------------------------------------------------------------
// Kernel 1: per-vocab precompute. Persistent blocks, double-buffered cp.async
// of raw fp32 emb tiles (64 rows x 64 floats, stride 68 -> conflict-free
// tf32 fragment loads), tf32 tensor-core MMA against U^T, fused epilogue.
// ---------------------------------------------------------------------------
__global__ void __launch_bounds__(128)
proj_kernel(const float* __restrict__ emb,
            const float* __restrict__ aw,  const float* __restrict__ ab,
            const float* __restrict__ W0,  const float* __restrict__ W1,
            const float* __restrict__ W2,  const float* __restrict__ W3,
            const float* __restrict__ W4) {
    __shared__ float sA[2][PTILE * PSTRIDE];   // 2 x 17408 B
    __shared__ float sU[24 * PSTRIDE];         // 6528 B (tf32-rounded bits)
    __shared__ float sab[5];
    const int tid  = threadIdx.x;
    const int lane = tid & 31;
    const int wid  = tid >> 5;

    // ---- stage U (weights) as tf32-rounded fp32: rows j=0..22, row 23 = 0 ----
    for (int e = tid; e < 24 * 64; e += 128) {
        int j = e >> 6, d = e & 63;
        float val = 0.0f;
        if (j < 5) {
            val = aw[j * 64 + d];
        } else if (j < 23) {
            int jq = j - 5;
            const float* Wsrc; int row;
            if      (jq < 2)  { Wsrc = W0; row = jq;      }
            else if (jq < 6)  { Wsrc = W1; row = jq - 2;  }
            else if (jq < 10) { Wsrc = W2; row = jq - 6;  }
            else if (jq < 12) { Wsrc = W3; row = jq - 10; }
            else              { Wsrc = W4; row = jq - 12; }
            val = Wsrc[row * 64 + d];
        }
        unsigned tv = tf32_rna(val);
        sU[j * PSTRIDE + d] = __uint_as_float(tv);
    }
    if (tid < 5) sab[tid] = ab[tid];

    // ---- tile issue: 64 rows x 16 chunks(16B) = 1024 copies, 8/thread ----
    auto issue_tile = [&](int t, int buf) {
        float* dstbase = sA[buf];
#pragma unroll
        for (int i = 0; i < 8; i++) {
            int q = i * 128 + tid;
            int r = q >> 4;
            int c = q & 15;
            int gr = t * PTILE + r;
            if (gr >= VV) gr = VV - 1;           // clamp; stores guarded later
            const float* src = emb + (size_t)gr * DD + c * 4;
            unsigned dst = (unsigned)__cvta_generic_to_shared(dstbase + r * PSTRIDE + c * 4);
            asm volatile("cp.async.cg.shared.global [%0], [%1], 16;\n"
                         :: "r"(dst), "l"(src) : "memory");
        }
        asm volatile("cp.async.commit_group;\n" ::: "memory");
    };

    int buf = 0;
    const int t0 = blockIdx.x;
    issue_tile(t0, 0);

    for (int t = t0; t < NTILES; t += PGRID) {
        const int tn = t + PGRID;
        const bool hasnext = (tn < NTILES);
        if (hasnext) issue_tile(tn, buf ^ 1);

        if (hasnext)
            asm volatile("cp.async.wait_group 1;\n" ::: "memory");
        else
            asm volatile("cp.async.wait_group 0;\n" ::: "memory");
        __syncthreads();   // tile (and sU on first iter) visible to all

        // ---- MMA: warp computes rows [wid*16, wid*16+16) of this tile ----
        const float* A = sA[buf];
        const int mr = wid * 16 + (lane >> 2);
        const int kc = lane & 3;
        float cacc[3][4];
#pragma unroll
        for (int nt = 0; nt < 3; nt++)
#pragma unroll
            for (int i = 0; i < 4; i++) cacc[nt][i] = 0.0f;

#pragma unroll
        for (int kt = 0; kt < 8; kt++) {
            const int k0 = kt * 8;
            unsigned a[4];
            a[0] = tf32_rna(A[mr * PSTRIDE + k0 + kc]);
            a[1] = tf32_rna(A[(mr + 8) * PSTRIDE + k0 + kc]);
            a[2] = tf32_rna(A[mr * PSTRIDE + k0 + kc + 4]);
            a[3] = tf32_rna(A[(mr + 8) * PSTRIDE + k0 + kc + 4]);
#pragma unroll
            for (int nt = 0; nt < 3; nt++) {
                unsigned b[2];
                b[0] = __float_as_uint(sU[(nt * 8 + (lane >> 2)) * PSTRIDE + k0 + kc]);
                b[1] = __float_as_uint(sU[(nt * 8 + (lane >> 2)) * PSTRIDE + k0 + kc + 4]);
                mma_tf32(cacc[nt], a, b);
            }
        }

        // ---- epilogue: transform j<5, pack fp16, store ----
        const int vbase = t * PTILE + wid * 16 + (lane >> 2);
#pragma unroll
        for (int h = 0; h < 2; h++) {
            int v = vbase + h * 8;
            if (v < VV) {
#pragma unroll
                for (int nt = 0; nt < 3; nt++) {
                    int j0 = nt * 8 + (lane & 3) * 2;
                    float x0 = cacc[nt][h * 2 + 0];
                    float x1 = cacc[nt][h * 2 + 1];
                    if (j0 < 5)     x0 = __expf(fast_tanh(x0 + sab[j0]));
                    if (j0 + 1 < 5) x1 = __expf(fast_tanh(x1 + sab[j0 + 1]));
                    __half2 hv = __floats2half2_rn(x0, x1);
                    *(__half2*)(g_proj + (size_t)v * ROWH + j0) = hv;
                }
            }
        }
        __syncthreads();   // all reads of buf done before it is re-issued
        buf ^= 1;
    }
}

// ---------------------------------------------------------------------------
// Kernel 2: main fused kernel (R15, measured at the L1tex replay floor).
// Two warps per batch element; 2-group cp.async gather; 48B smem rows.
// ---------------------------------------------------------------------------
__global__ void __launch_bounds__(128, 8)
main_kernel(const int*   __restrict__ x,
            const float* __restrict__ y,
            float* __restrict__ out) {
    __shared__ float stage_all[4][100 * MSTRIDE];  // per warp: 100 rows x 48B
    __shared__ int   sidx[4][100];
    __shared__ float partial[2][24];

    const int lane = threadIdx.x & 31;
    const int warp = threadIdx.x >> 5;
    const int bi   = warp >> 1;
    const int half = warp & 1;
    const int b    = blockIdx.x * 2 + bi;
    float* st = stage_all[warp];
    int*   si = sidx[warp];

    const int* xb = x + b * SS + half * 100;
#pragma unroll
    for (int c = 0; c < 4; c++) {
        int loc = c * 32 + lane;
        if (loc < 100) si[loc] = xb[loc];
    }
    __syncwarp();

    // ---- group A: rows 0..63 (192 copies) ----
#pragma unroll
    for (int i = 0; i < 6; i++) {
        int id = i * 32 + lane;
        int row = id / 3;
        int ch  = id - row * 3;
        int v   = si[row];
        const __half* src = g_proj + (size_t)v * ROWH + ch * 8;
        unsigned dst = (unsigned)__cvta_generic_to_shared(st + row * MSTRIDE + ch * 4);
        asm volatile("cp.async.cg.shared.global [%0], [%1], 16;\n"
                     :: "r"(dst), "l"(src) : "memory");
    }
    asm volatile("cp.async.commit_group;\n" ::: "memory");

    // ---- group B: rows 64..99 (108 copies) ----
#pragma unroll
    for (int i = 0; i < 4; i++) {
        int id = 192 + i * 32 + lane;
        if (id < 300) {
            int row = id / 3;
            int ch  = id - row * 3;
            int v   = si[row];
            const __half* src = g_proj + (size_t)v * ROWH + ch * 8;
            unsigned dst = (unsigned)__cvta_generic_to_shared(st + row * MSTRIDE + ch * 4);
            asm volatile("cp.async.cg.shared.global [%0], [%1], 16;\n"
                         :: "r"(dst), "l"(src) : "memory");
        }
    }
    asm volatile("cp.async.commit_group;\n" ::: "memory");

    float ls[5] = {0.f, 0.f, 0.f, 0.f, 0.f};
    float acc[18];
#pragma unroll
    for (int j = 0; j < 18; j++) acc[j] = 0.0f;

#pragma unroll
    for (int it = 0; it < 4; it++) {
        if (it == 0) {
            asm volatile("cp.async.wait_group 1;\n" ::: "memory");
            __syncwarp();
        }
        if (it == 2) {
            asm volatile("cp.async.wait_group 0;\n" ::: "memory");
            __syncwarp();
        }
        int row = it * 32 + lane;
        if (row < 100) {
            const float* rp = st + row * MSTRIDE;
            float4 cs[3];
            cs[0] = *(const float4*)(rp + 0);
            cs[1] = *(const float4*)(rp + 4);
            cs[2] = *(const float4*)(rp + 8);
            const __half2* h2 = (const __half2*)cs;
            float2 p[12];
#pragma unroll
            for (int i = 0; i < 12; i++) p[i] = __half22float2(h2[i]);
            ls[0] += p[0].x; ls[1] += p[0].y; ls[2] += p[1].x;
            ls[3] += p[1].y; ls[4] += p[2].x;
            acc[0]  = fmaf(p[0].x, p[2].y, acc[0]);
            acc[1]  = fmaf(p[0].x, p[3].x, acc[1]);
            acc[2]  = fmaf(p[0].y, p[3].y, acc[2]);
            acc[3]  = fmaf(p[0].y, p[4].x, acc[3]);
            acc[4]  = fmaf(p[0].y, p[4].y, acc[4]);
            acc[5]  = fmaf(p[0].y, p[5].x, acc[5]);
            acc[6]  = fmaf(p[1].x, p[5].y, acc[6]);
            acc[7]  = fmaf(p[1].x, p[6].x, acc[7]);
            acc[8]  = fmaf(p[1].x, p[6].y, acc[8]);
            acc[9]  = fmaf(p[1].x, p[7].x, acc[9]);
            acc[10] = fmaf(p[1].y, p[7].y, acc[10]);
            acc[11] = fmaf(p[1].y, p[8].x, acc[11]);
            acc[12] = fmaf(p[2].x, p[8].y, acc[12]);
            acc[13] = fmaf(p[2].x, p[9].x, acc[13]);
            acc[14] = fmaf(p[2].x, p[9].y, acc[14]);
            acc[15] = fmaf(p[2].x, p[10].x, acc[15]);
            acc[16] = fmaf(p[2].x, p[10].y, acc[16]);
            acc[17] = fmaf(p[2].x, p[11].x, acc[17]);
        }
    }

#pragma unroll
    for (int k = 0; k < 5; k++) {
#pragma unroll
        for (int o = 16; o > 0; o >>= 1)
            ls[k] += __shfl_xor_sync(0xffffffffu, ls[k], o);
    }
#pragma unroll
    for (int j = 0; j < 18; j++) {
#pragma unroll
        for (int o = 16; o > 0; o >>= 1)
            acc[j] += __shfl_xor_sync(0xffffffffu, acc[j], o);
    }

    if (half == 1) {
        if (lane < 5)  partial[bi][lane] = ls[lane];
        if (lane < 18) partial[bi][5 + lane] = acc[lane];
    }
    __syncthreads();
    if (half == 1) return;

#pragma unroll
    for (int k = 0; k < 5; k++) ls[k] += partial[bi][k];
#pragma unroll
    for (int j = 0; j < 18; j++) acc[j] += partial[bi][5 + j];

    float inv[5];
#pragma unroll
    for (int k = 0; k < 5; k++) inv[k] = 1.0f / ls[k];

    const int kmap[18] = {0,0, 1,1,1,1, 2,2,2,2, 3,3, 4,4,4,4,4,4};
    float outv[18];
#pragma unroll
    for (int j = 0; j < 18; j++) outv[j] = acc[j] * inv[kmap[j]];

    const float* yb = y + b * 18;
    const int AL[5] = {2, 4, 4, 2, 6};
    float loss = 0.0f;
    float logits[18];
    int base = 0;
#pragma unroll
    for (int i = 0; i < 5; i++) {
        const int L = AL[i];
        float m = outv[base];
#pragma unroll
        for (int jj = 1; jj < L; jj++) m = fmaxf(m, outv[base + jj]);
        float ssum = 0.0f, dy = 0.0f;
#pragma unroll
        for (int jj = 0; jj < L; jj++) {
            float e = __expf(outv[base + jj] - m);
            logits[base + jj] = e;
            ssum += e;
            dy = fmaf(yb[base + jj], outv[base + jj], dy);
        }
        float sinv = 1.0f / ssum;
#pragma unroll
        for (int jj = 0; jj < L; jj++) logits[base + jj] *= sinv;
        loss += m + __logf(ssum) - dy;
        base += L;
    }

    if (lane < 18) out[b * 18 + lane] = logits[lane];
    if (lane == 0) g_loss[b] = loss;
}

// ---------------------------------------------------------------------------
// Kernel 3: deterministic loss reduction
// ---------------------------------------------------------------------------
__global__ void loss_reduce(float* __restrict__ out_loss) {
    __shared__ float s[256];
    float v = 0.0f;
    for (int i = threadIdx.x; i < BB; i += 256) v += g_loss[i];
    s[threadIdx.x] = v;
    __syncthreads();
    for (int o = 128; o > 0; o >>= 1) {
        if (threadIdx.x < o) s[threadIdx.x] += s[threadIdx.x + o];
        __syncthreads();
    }
    if (threadIdx.x == 0) *out_loss = s[0] * (1.0f / (float)BB);
}

// ---------------------------------------------------------------------------
extern "C" void kernel_launch(void* const* d_in, const int* in_sizes, int n_in,
                              void* d_out, int out_size) {
    const int*   x   = (const int*)  d_in[0];
    const float* y   = (const float*)d_in[1];
    const float* emb = (const float*)d_in[2];
    const float* aw  = (const float*)d_in[3];
    const float* ab  = (const float*)d_in[4];
    const float* W0  = (const float*)d_in[5];
    const float* W1  = (const float*)d_in[6];
    const float* W2  = (const float*)d_in[7];
    const float* W3  = (const float*)d_in[8];
    const float* W4  = (const float*)d_in[9];
    float* out = (float*)d_out;

    proj_kernel<<<PGRID, 128>>>(emb, aw, ab, W0, W1, W2, W3, W4);
    main_kernel<<<BB / 2, 128>>>(x, y, out);
    loss_reduce<<<1, 256>>>(out + (out_size - 1));
}